// round 13
// baseline (speedup 1.0000x reference)
#include <cuda_runtime.h>
#include <math.h>

#define ULL unsigned long long

// ---------------- packed f32x2 helpers (sm_103a) ----------------
__device__ __forceinline__ ULL pack2(float x) {
    ULL d; asm("mov.b64 %0, {%1, %1};" : "=l"(d) : "f"(x)); return d;
}
__device__ __forceinline__ ULL fma2(ULL a, ULL b, ULL c) {
    ULL d; asm("fma.rn.f32x2 %0, %1, %2, %3;" : "=l"(d) : "l"(a), "l"(b), "l"(c)); return d;
}
__device__ __forceinline__ ULL add2(ULL a, ULL b) {
    ULL d; asm("add.rn.f32x2 %0, %1, %2;" : "=l"(d) : "l"(a), "l"(b)); return d;
}
__device__ __forceinline__ void unpack2(ULL v, float& lo, float& hi) {
    asm("mov.b64 {%0, %1}, %2;" : "=f"(lo), "=f"(hi) : "l"(v));
}

// mish(x) = x * tanh(softplus(x)) = x * (e^2x + 2e^x) / (e^2x + 2e^x + 2)
__device__ __forceinline__ float mish_f(float v) {
    if (v > 20.f) return v;
    float e = expf(v);
    float n = e * e + 2.f * e;
    return v * (n / (n + 2.f));
}

constexpr int HID  = 256;
constexpr int ADIM = 16;
constexpr int SDIM = 64;
constexpr int TDIM = 32;
constexpr int TS   = 100;
constexpr int MT   = 16;     // batch rows per CTA
constexpr int HS   = 260;    // compact activation stride (floats)
constexpr int HSD  = 520;    // duplicated activation stride (floats)

struct __align__(16) Smem {
    float hAdup[MT * HSD];    // duplicated activations (GEMM inputs)
    float hBdup[MT * HSD];
    float hC[MT * HS];        // compact (layer-4 input)
    float S[MT * HID];        // state @ W1_state + b1 (step-invariant, compact)
    float W1x[ADIM * HID];    // W1 rows 0..15 (x part)
    float W4T[ADIM * HS];     // W4 transposed
    float x2[MT * 2 * ADIM];  // x, duplicated: x2[row][2j]=x2[row][2j+1]
    float b2[HID], b3[HID], b4[ADIM];
    float r1[TS], r2[TS], c1[TS], c2[TS], stdv[TS];
    float emb[TDIM], t1[HID], tpart[HID], temb[TDIM], tcon[HID];
};

// Load 16 consecutive K-rows of weights (cols 4tx..4tx+3) for chunk ch.
#define LOADBUF(buf, ch) {                                                   \
    int c0_ = (ch) > 15 ? 15 : (ch);                                         \
    _Pragma("unroll")                                                        \
    for (int u_ = 0; u_ < 16; u_++)                                          \
        buf[u_] = __ldg(wp + (c0_ * 16 + u_) * 64);                          \
}

// Accumulate one 16-K chunk from duplicated activations. Zero MOVs.
#define COMPUTE(buf, ch) {                                                   \
    _Pragma("unroll")                                                        \
    for (int r_ = 0; r_ < 4; r_++) {                                         \
        const float* ar_ = a0 + r_ * HSD + (ch) * 32;                        \
        _Pragma("unroll")                                                    \
        for (int i_ = 0; i_ < 8; i_++) {                                     \
            ulonglong2 A4_ = *reinterpret_cast<const ulonglong2*>(ar_ + 4 * i_); \
            acc[r_][0] = fma2(A4_.x, buf[2 * i_].x,     acc[r_][0]);         \
            acc[r_][1] = fma2(A4_.x, buf[2 * i_].y,     acc[r_][1]);         \
            acc[r_][0] = fma2(A4_.y, buf[2 * i_ + 1].x, acc[r_][0]);         \
            acc[r_][1] = fma2(A4_.y, buf[2 * i_ + 1].y, acc[r_][1]);         \
        }                                                                    \
    }                                                                        \
}

// C[16 x 256] = mish( A_dup[16 x 512] @ W[256 x 256] + bias )
// Weights streamed from L2, 16-K double-buffered chunks (manual 2x unroll: no
// buffer-copy MOVs, prefetch distance = 1 chunk ~ 370 wall cyc > L2 latency).
template <bool DUP_OUT>
__device__ __forceinline__ void gemm_hidden(const float* __restrict__ Wg,
                                            const float* bsm,
                                            const float* src, float* dst,
                                            int tx, int ty) {
    ULL acc[4][2];
    {
        ulonglong2 bv = *(reinterpret_cast<const ulonglong2*>(bsm) + tx);
        #pragma unroll
        for (int r = 0; r < 4; r++) { acc[r][0] = bv.x; acc[r][1] = bv.y; }
    }
    const ulonglong2* wp = reinterpret_cast<const ulonglong2*>(Wg) + tx;
    const float* a0 = src + (ty << 2) * HSD;

    ulonglong2 bufA[16], bufB[16];
    LOADBUF(bufA, 0);

    #pragma unroll 1
    for (int j = 0; j < 8; j++) {
        LOADBUF(bufB, 2 * j + 1);
        COMPUTE(bufA, 2 * j);
        LOADBUF(bufA, 2 * j + 2);
        COMPUTE(bufB, 2 * j + 1);
    }

    #pragma unroll
    for (int r = 0; r < 4; r++) {
        float a, b, c, d;
        unpack2(acc[r][0], a, b);
        unpack2(acc[r][1], c, d);
        float ma = mish_f(a), mb = mish_f(b), mc = mish_f(c), md = mish_f(d);
        if (DUP_OUT) {
            float* d0 = dst + (4 * ty + r) * HSD + (tx << 3);
            *reinterpret_cast<float4*>(d0)     = make_float4(ma, ma, mb, mb);
            *reinterpret_cast<float4*>(d0 + 4) = make_float4(mc, mc, md, md);
        } else {
            *reinterpret_cast<float4*>(dst + (4 * ty + r) * HS + (tx << 2)) =
                make_float4(ma, mb, mc, md);
        }
    }
}

__global__ __launch_bounds__(256, 1)
void diffusion_kernel(const float* __restrict__ state,
                      const float* __restrict__ x_init,
                      const float* __restrict__ noise,
                      const float* __restrict__ tW1g, const float* __restrict__ tb1g,
                      const float* __restrict__ tW2g, const float* __restrict__ tb2g,
                      const float* __restrict__ W1,   const float* __restrict__ b1,
                      const float* __restrict__ W2,   const float* __restrict__ b2g,
                      const float* __restrict__ W3,   const float* __restrict__ b3g,
                      const float* __restrict__ W4,   const float* __restrict__ b4g,
                      float* __restrict__ out) {
    extern __shared__ char smem_raw[];
    Smem* s = reinterpret_cast<Smem*>(smem_raw);
    const int tid = threadIdx.x;
    const int tx = tid & 63, ty = tid >> 6;
    const int row0 = blockIdx.x * MT;
    const int um = tid >> 4, uj = tid & 15;

    // ---- cache the small weights / biases in smem ----
    for (int i = tid; i < ADIM * HID; i += 256) s->W1x[i] = W1[i];
    for (int i = tid; i < HID; i += 256) { s->b2[i] = b2g[i]; s->b3[i] = b3g[i]; }
    if (tid < ADIM) s->b4[tid] = b4g[tid];
    for (int i = tid; i < HID * ADIM; i += 256) {   // W4 [256x16] -> W4T [16][260]
        int k = i >> 4, j = i & 15;
        s->W4T[j * HS + k] = W4[i];
    }
    {   // x duplicated
        float v = x_init[row0 * ADIM + tid];
        s->x2[um * 2 * ADIM + 2 * uj]     = v;
        s->x2[um * 2 * ADIM + 2 * uj + 1] = v;
    }
    for (int i = tid; i < MT * SDIM; i += 256) s->hBdup[i] = state[row0 * SDIM + i]; // scratch

    // ---- schedule via closed-form cumprod ----
    if (tid < TS) {
        const double T = 100.0, bmax = 10.0, bmin = 0.1;
        double n1 = (double)(tid + 1), n0 = (double)tid;
        double g1 = -bmin * n1 / T - 0.5 * (bmax - bmin) * n1 * n1 / (T * T);
        double g0 = -bmin * n0 / T - 0.5 * (bmax - bmin) * n0 * n0 / (T * T);
        double ac = exp(g1), acp = exp(g0);
        double alpha = exp(g1 - g0);
        double beta = 1.0 - alpha;
        s->r1[tid] = (float)sqrt(1.0 / ac);
        s->r2[tid] = (float)sqrt(1.0 / ac - 1.0);
        s->c1[tid] = (float)(beta * sqrt(acp) / (1.0 - ac));
        s->c2[tid] = (float)((1.0 - acp) * sqrt(alpha) / (1.0 - ac));
        double v = beta * (1.0 - acp) / (1.0 - ac);
        if (v < 1e-20) v = 1e-20;
        s->stdv[tid] = expf(0.5f * (float)log(v));
    }
    __syncthreads();

    // ---- S = state @ W1[48:112] + b1 (once; compact output) ----
    {
        ULL acc[4][2];
        ulonglong2 bv = __ldg(reinterpret_cast<const ulonglong2*>(b1) + tx);
        #pragma unroll
        for (int r = 0; r < 4; r++) { acc[r][0] = bv.x; acc[r][1] = bv.y; }
        const ulonglong2* wp = reinterpret_cast<const ulonglong2*>(W1 + (ADIM + TDIM) * HID) + tx;
        const float* a0 = s->hBdup + (ty * 4) * SDIM;
        for (int k = 0; k < SDIM; k++) {
            ulonglong2 w = __ldg(wp + k * 64);
            #pragma unroll
            for (int r = 0; r < 4; r++) {
                ULL a2 = pack2(a0[r * SDIM + k]);
                acc[r][0] = fma2(a2, w.x, acc[r][0]);
                acc[r][1] = fma2(a2, w.y, acc[r][1]);
            }
        }
        #pragma unroll
        for (int r = 0; r < 4; r++) {
            float a, b, c, d;
            unpack2(acc[r][0], a, b);
            unpack2(acc[r][1], c, d);
            *reinterpret_cast<float4*>(s->S + (4 * ty + r) * HID + 4 * tx) = make_float4(a, b, c, d);
        }
    }
    __syncthreads();

    // ---- 100-step reverse diffusion ----
    for (int sstep = 0; sstep < TS; sstep++) {
        int i = TS - 1 - sstep;

        if (tid < 16) {
            float f = expf((float)tid * -0.61402269146507890f);  // -ln(10000)/15
            float ang = (float)i * f;
            s->emb[tid] = sinf(ang);
            s->emb[tid + 16] = cosf(ang);
        }
        __syncthreads();

        // time MLP layer 1 (weights from L2/L1, coalesced)
        {
            float a = __ldg(tb1g + tid);
            #pragma unroll 8
            for (int k = 0; k < TDIM; k++) a += s->emb[k] * __ldg(tW1g + k * HID + tid);
            s->t1[tid] = mish_f(a);
        }
        __syncthreads();

        // time MLP layer 2 (8-way K-split + reduce)
        {
            int j = tid & 31, p = tid >> 5;
            float a = 0.f;
            const float* tv = s->t1 + p * 32;
            #pragma unroll 8
            for (int k = 0; k < 32; k++) a += tv[k] * __ldg(tW2g + (p * 32 + k) * TDIM + j);
            s->tpart[tid] = a;
        }
        __syncthreads();
        if (tid < 32) {
            float a = __ldg(tb2g + tid);
            #pragma unroll
            for (int p = 0; p < 8; p++) a += s->tpart[p * 32 + tid];
            s->temb[tid] = a;
        }
        __syncthreads();

        // tcon = temb @ W1[16:48] (from L2/L1)
        {
            float a = 0.f;
            #pragma unroll 8
            for (int k = 0; k < TDIM; k++) a += s->temb[k] * __ldg(W1 + (ADIM + k) * HID + tid);
            s->tcon[tid] = a;
        }
        __syncthreads();

        // layer 1: hAdup = mish( x @ W1x + S + tcon )  [dup output]
        {
            ULL acc[4][2];
            ulonglong2 tc = *(reinterpret_cast<const ulonglong2*>(s->tcon) + tx);
            #pragma unroll
            for (int r = 0; r < 4; r++) {
                ulonglong2 sv = *(reinterpret_cast<const ulonglong2*>(s->S + (4 * ty + r) * HID) + tx);
                acc[r][0] = add2(sv.x, tc.x);
                acc[r][1] = add2(sv.y, tc.y);
            }
            const ulonglong2* wx = reinterpret_cast<const ulonglong2*>(s->W1x) + tx;
            #pragma unroll
            for (int i2 = 0; i2 < 8; i2++) {
                ulonglong2 w0 = wx[(2 * i2) * 64];
                ulonglong2 w1 = wx[(2 * i2 + 1) * 64];
                #pragma unroll
                for (int r = 0; r < 4; r++) {
                    ulonglong2 A4 = *reinterpret_cast<const ulonglong2*>(
                        s->x2 + (4 * ty + r) * 2 * ADIM + 4 * i2);
                    acc[r][0] = fma2(A4.x, w0.x, acc[r][0]);
                    acc[r][1] = fma2(A4.x, w0.y, acc[r][1]);
                    acc[r][0] = fma2(A4.y, w1.x, acc[r][0]);
                    acc[r][1] = fma2(A4.y, w1.y, acc[r][1]);
                }
            }
            #pragma unroll
            for (int r = 0; r < 4; r++) {
                float a, b, c, d;
                unpack2(acc[r][0], a, b);
                unpack2(acc[r][1], c, d);
                float ma = mish_f(a), mb = mish_f(b), mc = mish_f(c), md = mish_f(d);
                float* d0 = s->hAdup + (4 * ty + r) * HSD + (tx << 3);
                *reinterpret_cast<float4*>(d0)     = make_float4(ma, ma, mb, mb);
                *reinterpret_cast<float4*>(d0 + 4) = make_float4(mc, mc, md, md);
            }
        }
        __syncthreads();

        gemm_hidden<true >(W2, s->b2, s->hAdup, s->hBdup, tx, ty);  // layer 2 (dup out)
        __syncthreads();
        gemm_hidden<false>(W3, s->b3, s->hBdup, s->hC,    tx, ty);  // layer 3 (compact out)
        __syncthreads();

        // layer 4 (eps) + posterior update
        {
            float acc = s->b4[uj];
            const float* hr = s->hC + um * HS;
            const float* wr = s->W4T + uj * HS;
            #pragma unroll 8
            for (int k = 0; k < HID; k += 4) {
                float4 h4 = *reinterpret_cast<const float4*>(hr + k);
                float4 w4 = *reinterpret_cast<const float4*>(wr + k);
                acc += h4.x * w4.x + h4.y * w4.y + h4.z * w4.z + h4.w * w4.w;
            }
            float xv = s->x2[um * 2 * ADIM + 2 * uj];
            float xr = s->r1[i] * xv - s->r2[i] * acc;
            xr = fminf(fmaxf(xr, -1.f), 1.f);
            float xn = s->c1[i] * xr + s->c2[i] * xv;
            if (i != 0)
                xn += s->stdv[i] * noise[((size_t)sstep * 2048 + row0 + um) * ADIM + uj];
            s->x2[um * 2 * ADIM + 2 * uj]     = xn;
            s->x2[um * 2 * ADIM + 2 * uj + 1] = xn;
        }
        __syncthreads();
    }

    float xv = s->x2[um * 2 * ADIM + 2 * uj];
    out[(row0 + um) * ADIM + uj] = fminf(fmaxf(xv, -1.f), 1.f);
}

extern "C" void kernel_launch(void* const* d_in, const int* in_sizes, int n_in,
                              void* d_out, int out_size) {
    (void)in_sizes; (void)n_in; (void)out_size;
    cudaFuncSetAttribute(diffusion_kernel,
                         cudaFuncAttributeMaxDynamicSharedMemorySize,
                         (int)sizeof(Smem));
    diffusion_kernel<<<128, 256, sizeof(Smem)>>>(
        (const float*)d_in[0],  // state
        (const float*)d_in[1],  // x_init
        (const float*)d_in[2],  // noise
        (const float*)d_in[3],  // time_W1
        (const float*)d_in[4],  // time_b1
        (const float*)d_in[5],  // time_W2
        (const float*)d_in[6],  // time_b2
        (const float*)d_in[7],  // W1
        (const float*)d_in[8],  // b1
        (const float*)d_in[9],  // W2
        (const float*)d_in[10], // b2
        (const float*)d_in[11], // W3
        (const float*)d_in[12], // b3
        (const float*)d_in[13], // W4
        (const float*)d_in[14], // b4
        (float*)d_out);
}